// round 10
// baseline (speedup 1.0000x reference)
#include <cuda_runtime.h>
#include <math.h>

#define NEG_SLOPE 0.1f

// Scratch (__device__ globals: alloc-free rule)
__device__ float g_dvec[16 * 512];
__device__ float g_kern[16 * 576];              // [b][c*9 + i*3 + j]
__device__ float g_att [16 * 64];
__device__ unsigned long long g_wdup[64 * 64];  // [c][o] = {W_conv[o][c], W_conv[o][c]}

__device__ __forceinline__ float lrelu(float x) { return x >= 0.f ? x : NEG_SLOPE * x; }

// ---- f32x2 packed helpers (sm_103a FFMA2) ----
__device__ __forceinline__ unsigned long long pk2(float lo, float hi) {
    unsigned long long r;
    asm("mov.b64 %0, {%1, %2};" : "=l"(r) : "f"(lo), "f"(hi));
    return r;
}
__device__ __forceinline__ void upk2(unsigned long long v, float& lo, float& hi) {
    asm("mov.b64 {%0, %1}, %2;" : "=f"(lo), "=f"(hi) : "l"(v));
}
__device__ __forceinline__ unsigned long long ffma2(unsigned long long a,
                                                    unsigned long long b,
                                                    unsigned long long c) {
    unsigned long long d;
    asm("fma.rn.f32x2 %0, %1, %2, %3;" : "=l"(d) : "l"(a), "l"(b), "l"(c));
    return d;
}

// ============================================================================
// Kernel A1: dvec = mean(deg over 8x8). 1024 blocks x 256 threads,
// one (b,d) row per warp -> 8192 warps, fully latency-hidden.
// ============================================================================
__global__ void __launch_bounds__(256) mean_kernel(const float* __restrict__ deg)
{
    const int lane = threadIdx.x & 31;
    const int gw   = (blockIdx.x * 256 + threadIdx.x) >> 5;   // 0..8191
    const int b = gw >> 9;
    const int d = gw & 511;
    const float* p = deg + ((size_t)b * 512 + d) * 64;
    float s = p[lane] + p[lane + 32];
    #pragma unroll
    for (int off = 16; off > 0; off >>= 1)
        s += __shfl_xor_sync(0xffffffffu, s, off);
    if (lane == 0) g_dvec[b * 512 + d] = s * (1.0f / 64.0f);
}

// ============================================================================
// Kernel A2: GEMV chains -> g_kern, g_att; also builds g_wdup (dup-packed
// transposed W_conv). 16 blocks x 512 threads.
// ============================================================================
__global__ void __launch_bounds__(512) prep_kernel(
    const float* __restrict__ W_size,  // [64,512]
    const float* __restrict__ W_k1,    // [8,64]
    const float* __restrict__ W_k2,    // [576,8]
    const float* __restrict__ W_ac,    // [64,512]
    const float* __restrict__ W_du1,   // [8,64]
    const float* __restrict__ W_du2,   // [64,8]
    const float* __restrict__ W_conv)  // [64,64]
{
    const int b   = blockIdx.x;
    const int tid = threadIdx.x;

    // Build g_wdup: block b covers 256 entries (16*256 = 4096).
    if (tid < 256) {
        const int idx = b * 256 + tid;          // [c][o]
        const int c = idx >> 6, o = idx & 63;
        const float w = W_conv[o * 64 + c];     // L2-resident, tiny
        g_wdup[idx] = pk2(w, w);
    }

    __shared__ float dvecS[512];
    __shared__ float partF[512];   // [p][c] = [8][64]
    __shared__ float partA[512];
    __shared__ float fS[64], faS[64];
    __shared__ float hS[8], hdS[8];

    dvecS[tid] = g_dvec[b * 512 + tid];
    __syncthreads();

    // f, fa: split-K over 8 partials
    {
        const int p = tid >> 6;     // 0..7
        const int c = tid & 63;
        const int base = p * 64;
        float sf = 0.f, sa = 0.f;
        #pragma unroll 8
        for (int dd = 0; dd < 64; ++dd) {
            float x = dvecS[base + dd];
            sf = fmaf(x, W_size[c * 512 + base + dd], sf);
            sa = fmaf(x, W_ac  [c * 512 + base + dd], sa);
        }
        partF[p * 64 + c] = sf;
        partA[p * 64 + c] = sa;
    }
    __syncthreads();
    if (tid < 64) {
        float sf = 0.f, sa = 0.f;
        #pragma unroll
        for (int p = 0; p < 8; ++p) { sf += partF[p * 64 + tid]; sa += partA[p * 64 + tid]; }
        fS[tid] = sf;
        faS[tid] = sa;
    }
    __syncthreads();

    if (tid < 8) {
        float s = 0.f;
        #pragma unroll 16
        for (int c = 0; c < 64; ++c) s = fmaf(fS[c], W_k1[tid * 64 + c], s);
        hS[tid] = lrelu(s);
    } else if (tid >= 32 && tid < 40) {
        const int j = tid - 32;
        float s = 0.f;
        #pragma unroll 16
        for (int c = 0; c < 64; ++c) s = fmaf(faS[c], W_du1[j * 64 + c], s);
        hdS[j] = lrelu(s);
    }
    __syncthreads();

    for (int i = tid; i < 576; i += 512) {
        float s = 0.f;
        #pragma unroll
        for (int j = 0; j < 8; ++j) s = fmaf(hS[j], W_k2[i * 8 + j], s);
        g_kern[b * 576 + i] = s;
    }
    if (tid < 64) {
        float s = 0.f;
        #pragma unroll
        for (int j = 0; j < 8; ++j) s = fmaf(hdS[j], W_du2[tid * 8 + j], s);
        g_att[b * 64 + tid] = 1.0f / (1.0f + expf(-s));
    }
}

// ============================================================================
// Kernel B: fused depthwise-3x3 + lrelu + 1x1 mix + bias + feat*att.
// Block = (b, 2 output rows). 512 threads. ~101 KB dyn smem, 2 CTA/SM.
//   Stage 1: dw[row][c][w] fp32 for 2 rows; 4 input rows loaded.
//   Stage 2: 8o x 4w per thread per row. Pre-duplicated packed weights in
//            smem (WdS, broadcast LDS.128) -> inner loop is pure LDS+FFMA2,
//            zero packing MOVs. dw fetch uses the CORRECT c*32 stride.
// grid = 16*64 = 1024
// ============================================================================
__global__ void __launch_bounds__(512, 2) main_kernel(
    const float* __restrict__ feat,    // [16,64,128,128]
    const float* __restrict__ b_conv,  // [64]
    float* __restrict__ out)
{
    extern __shared__ float smemF[];
    float* dwS = smemF;                                       // [2][64][128] = 16384 f (64 KB)
    unsigned long long* WdS = (unsigned long long*)(smemF + 16384);  // [c][o] 4096 u64 (32 KB)
    float* kS    = smemF + 16384 + 8192;   // 576
    float* attS  = kS + 576;               // 64
    float* biasS = attS + 64;              // 64

    const int tid  = threadIdx.x;
    const int bid  = blockIdx.x;
    const int b    = bid >> 6;
    const int h0   = (bid & 63) * 2;
    const int lane = tid & 31;
    const int wid  = tid >> 5;   // 0..15

    // --- stage shared operands (all coalesced) ---
    #pragma unroll
    for (int i = 0; i < 8; ++i) WdS[i * 512 + tid] = g_wdup[i * 512 + tid];
    for (int i = tid; i < 576; i += 512) kS[i] = g_kern[b * 576 + i];
    if (tid < 64) { attS[tid] = g_att[b * 64 + tid]; biasS[tid] = b_conv[tid]; }
    __syncthreads();

    // --- Stage 1: depthwise 3x3 + lrelu for both rows ---
    const float4* feat4 = (const float4*)feat;
    #pragma unroll
    for (int cp = 0; cp < 4; ++cp) {
        const int c = cp * 16 + wid;
        float4 v[4];
        float lf[4], rg[4];
        #pragma unroll
        for (int ri = 0; ri < 4; ++ri) {
            const int r = h0 - 1 + ri;
            if (r >= 0 && r < 128)
                v[ri] = feat4[(((size_t)b * 64 + c) * 128 + r) * 32 + lane];
            else
                v[ri] = make_float4(0.f, 0.f, 0.f, 0.f);
            lf[ri] = __shfl_up_sync(0xffffffffu, v[ri].w, 1);
            rg[ri] = __shfl_down_sync(0xffffffffu, v[ri].x, 1);
            if (lane == 0)  lf[ri] = 0.f;
            if (lane == 31) rg[ri] = 0.f;
        }
        #pragma unroll
        for (int row = 0; row < 2; ++row) {
            float4 a = make_float4(0.f, 0.f, 0.f, 0.f);
            #pragma unroll
            for (int kr = 0; kr < 3; ++kr) {
                const int ri = row + kr;
                const float q0 = kS[c * 9 + kr * 3 + 0];
                const float q1 = kS[c * 9 + kr * 3 + 1];
                const float q2 = kS[c * 9 + kr * 3 + 2];
                a.x = fmaf(q0, lf[ri],   fmaf(q1, v[ri].x, fmaf(q2, v[ri].y, a.x)));
                a.y = fmaf(q0, v[ri].x,  fmaf(q1, v[ri].y, fmaf(q2, v[ri].z, a.y)));
                a.z = fmaf(q0, v[ri].y,  fmaf(q1, v[ri].z, fmaf(q2, v[ri].w, a.z)));
                a.w = fmaf(q0, v[ri].z,  fmaf(q1, v[ri].w, fmaf(q2, rg[ri],  a.w)));
            }
            a.x = lrelu(a.x); a.y = lrelu(a.y); a.z = lrelu(a.z); a.w = lrelu(a.w);
            ((float4*)(dwS + row * 8192))[c * 32 + lane] = a;
        }
    }
    __syncthreads();

    // --- Stage 2: 1x1 mix, 8 o-channels x 4 pixels per thread, one row each ---
    const int w_t = tid & 31;          // pixel group (4 px)
    const int og  = (tid >> 5) & 7;    // warp-uniform
    const int row = tid >> 8;          // warp-uniform
    const int o0  = og * 8;
    const int h   = h0 + row;

    const ulonglong2* dw2 = (const ulonglong2*)(dwS + row * 8192);

    unsigned long long acc[8][2];
    #pragma unroll
    for (int i = 0; i < 8; ++i) { acc[i][0] = 0ull; acc[i][1] = 0ull; }

    #pragma unroll 4
    for (int c = 0; c < 64; ++c) {
        ulonglong2 d = dw2[c * 32 + w_t];   // CORRECT stride: 128 f = 32 ulonglong2
        const ulonglong2* wp = (const ulonglong2*)(WdS + c * 64 + o0);  // broadcast
        ulonglong2 w01 = wp[0];
        ulonglong2 w23 = wp[1];
        ulonglong2 w45 = wp[2];
        ulonglong2 w67 = wp[3];
        acc[0][0] = ffma2(w01.x, d.x, acc[0][0]); acc[0][1] = ffma2(w01.x, d.y, acc[0][1]);
        acc[1][0] = ffma2(w01.y, d.x, acc[1][0]); acc[1][1] = ffma2(w01.y, d.y, acc[1][1]);
        acc[2][0] = ffma2(w23.x, d.x, acc[2][0]); acc[2][1] = ffma2(w23.x, d.y, acc[2][1]);
        acc[3][0] = ffma2(w23.y, d.x, acc[3][0]); acc[3][1] = ffma2(w23.y, d.y, acc[3][1]);
        acc[4][0] = ffma2(w45.x, d.x, acc[4][0]); acc[4][1] = ffma2(w45.x, d.y, acc[4][1]);
        acc[5][0] = ffma2(w45.y, d.x, acc[5][0]); acc[5][1] = ffma2(w45.y, d.y, acc[5][1]);
        acc[6][0] = ffma2(w67.x, d.x, acc[6][0]); acc[6][1] = ffma2(w67.x, d.y, acc[6][1]);
        acc[7][0] = ffma2(w67.y, d.x, acc[7][0]); acc[7][1] = ffma2(w67.y, d.y, acc[7][1]);
    }

    // --- epilogue: + bias + feat*att, coalesced float4 stores ---
    #pragma unroll
    for (int oo = 0; oo < 8; ++oo) {
        const int o = o0 + oo;
        float r0, r1, r2, r3;
        upk2(acc[oo][0], r0, r1);
        upk2(acc[oo][1], r2, r3);
        const float bb = biasS[o];
        const float aa = attS[o];
        const size_t idx4 = (((size_t)b * 64 + o) * 128 + h) * 32 + w_t;
        float4 fv = ((const float4*)feat)[idx4];
        float4 ov;
        ov.x = r0 + bb + fv.x * aa;
        ov.y = r1 + bb + fv.y * aa;
        ov.z = r2 + bb + fv.z * aa;
        ov.w = r3 + bb + fv.w * aa;
        ((float4*)out)[idx4] = ov;
    }
}

extern "C" void kernel_launch(void* const* d_in, const int* in_sizes, int n_in,
                              void* d_out, int out_size) {
    (void)in_sizes; (void)n_in; (void)out_size;
    const float* feat   = (const float*)d_in[0];
    const float* deg    = (const float*)d_in[1];
    const float* W_size = (const float*)d_in[2];
    const float* W_k1   = (const float*)d_in[3];
    const float* W_k2   = (const float*)d_in[4];
    const float* W_conv = (const float*)d_in[5];
    const float* b_conv = (const float*)d_in[6];
    const float* W_ac   = (const float*)d_in[7];
    const float* W_du1  = (const float*)d_in[8];
    const float* W_du2  = (const float*)d_in[9];
    float* out = (float*)d_out;

    const int kMainSmem = (16384 + 8192 * 2 + 704) * 4;   // 101,184 B
    (void)cudaFuncSetAttribute(main_kernel,
                               cudaFuncAttributeMaxDynamicSharedMemorySize, kMainSmem);

    mean_kernel<<<1024, 256>>>(deg);
    prep_kernel<<<16, 512>>>(W_size, W_k1, W_k2, W_ac, W_du1, W_du2, W_conv);
    main_kernel<<<16 * 64, 512, kMainSmem>>>(feat, b_conv, out);
}

// round 13
// speedup vs baseline: 1.5452x; 1.5452x over previous
#include <cuda_runtime.h>
#include <cuda_bf16.h>
#include <math.h>
#include <stdint.h>

#define NEG_SLOPE 0.1f

// Scratch (__device__ globals: alloc-free rule)
__device__ float    g_dvec[16 * 512];
__device__ float    g_kern[16 * 576];   // [b][c*9 + i*3 + j]
__device__ float    g_att [16 * 64];
__device__ uint32_t g_wswz[2048];       // bf16x2 swizzled W image [o][c], 128B rows

__device__ __forceinline__ float lrelu(float x) { return x >= 0.f ? x : NEG_SLOPE * x; }

// pack {lo, hi} floats -> bf16x2 (lo in lower 16 bits)
__device__ __forceinline__ uint32_t bf2(float lo, float hi) {
    uint32_t r;
    asm("cvt.rn.bf16x2.f32 %0, %1, %2;" : "=r"(r) : "f"(hi), "f"(lo));
    return r;
}
__device__ __forceinline__ uint32_t swz(uint32_t byte_off) {   // 128B-row swizzle
    return byte_off ^ ((byte_off >> 3) & 0x70);
}
__device__ __forceinline__ uint32_t smem_u32(const void* p) {
    uint32_t a;
    asm("{ .reg .u64 t; cvta.to.shared.u64 t, %1; cvt.u32.u64 %0, t; }" : "=r"(a) : "l"(p));
    return a;
}

__device__ __forceinline__ void ldm_x4(uint32_t& r0, uint32_t& r1, uint32_t& r2,
                                       uint32_t& r3, uint32_t addr) {
    asm volatile("ldmatrix.sync.aligned.m8n8.x4.shared.b16 {%0,%1,%2,%3}, [%4];"
                 : "=r"(r0), "=r"(r1), "=r"(r2), "=r"(r3) : "r"(addr));
}
__device__ __forceinline__ void ldm_x4_t(uint32_t& r0, uint32_t& r1, uint32_t& r2,
                                         uint32_t& r3, uint32_t addr) {
    asm volatile("ldmatrix.sync.aligned.m8n8.x4.trans.shared.b16 {%0,%1,%2,%3}, [%4];"
                 : "=r"(r0), "=r"(r1), "=r"(r2), "=r"(r3) : "r"(addr));
}
__device__ __forceinline__ void mma_bf16(float* c, uint32_t a0, uint32_t a1,
                                         uint32_t a2, uint32_t a3,
                                         uint32_t b0, uint32_t b1) {
    asm volatile(
        "mma.sync.aligned.m16n8k16.row.col.f32.bf16.bf16.f32 "
        "{%0,%1,%2,%3}, {%4,%5,%6,%7}, {%8,%9}, {%0,%1,%2,%3};"
        : "+f"(c[0]), "+f"(c[1]), "+f"(c[2]), "+f"(c[3])
        : "r"(a0), "r"(a1), "r"(a2), "r"(a3), "r"(b0), "r"(b1));
}

// ============================================================================
// Kernel A1: dvec = mean(deg over 8x8).
// ============================================================================
__global__ void __launch_bounds__(256) mean_kernel(const float* __restrict__ deg)
{
    const int lane = threadIdx.x & 31;
    const int gw   = (blockIdx.x * 256 + threadIdx.x) >> 5;   // 0..8191
    const int b = gw >> 9;
    const int d = gw & 511;
    const float* p = deg + ((size_t)b * 512 + d) * 64;
    float s = p[lane] + p[lane + 32];
    #pragma unroll
    for (int off = 16; off > 0; off >>= 1)
        s += __shfl_xor_sync(0xffffffffu, s, off);
    if (lane == 0) g_dvec[b * 512 + d] = s * (1.0f / 64.0f);
}

// ============================================================================
// Kernel A2: GEMV chains -> g_kern, g_att; block 0 builds the swizzled bf16
// W_conv image. 16 blocks x 512 threads.
// ============================================================================
__global__ void __launch_bounds__(512) prep_kernel(
    const float* __restrict__ W_size,  // [64,512]
    const float* __restrict__ W_k1,    // [8,64]
    const float* __restrict__ W_k2,    // [576,8]
    const float* __restrict__ W_ac,    // [64,512]
    const float* __restrict__ W_du1,   // [8,64]
    const float* __restrict__ W_du2,   // [64,8]
    const float* __restrict__ W_conv)  // [64,64]
{
    const int b   = blockIdx.x;
    const int tid = threadIdx.x;

    if (b == 0) {
        // bf16 pair (o, 2c2..2c2+1) at swz(o*128 + c2*4)
        #pragma unroll
        for (int k = 0; k < 4; ++k) {
            const int idx = tid + k * 512;        // 0..2047
            const int o  = idx >> 5;
            const int c2 = idx & 31;
            const float lo = W_conv[o * 64 + 2 * c2];
            const float hi = W_conv[o * 64 + 2 * c2 + 1];
            g_wswz[swz((uint32_t)(o * 128 + c2 * 4)) >> 2] = bf2(lo, hi);
        }
    }

    __shared__ float dvecS[512];
    __shared__ float partF[512];
    __shared__ float partA[512];
    __shared__ float fS[64], faS[64];
    __shared__ float hS[8], hdS[8];

    dvecS[tid] = g_dvec[b * 512 + tid];
    __syncthreads();

    {
        const int p = tid >> 6;
        const int c = tid & 63;
        const int base = p * 64;
        float sf = 0.f, sa = 0.f;
        #pragma unroll 8
        for (int dd = 0; dd < 64; ++dd) {
            float x = dvecS[base + dd];
            sf = fmaf(x, W_size[c * 512 + base + dd], sf);
            sa = fmaf(x, W_ac  [c * 512 + base + dd], sa);
        }
        partF[p * 64 + c] = sf;
        partA[p * 64 + c] = sa;
    }
    __syncthreads();
    if (tid < 64) {
        float sf = 0.f, sa = 0.f;
        #pragma unroll
        for (int p = 0; p < 8; ++p) { sf += partF[p * 64 + tid]; sa += partA[p * 64 + tid]; }
        fS[tid] = sf;
        faS[tid] = sa;
    }
    __syncthreads();

    if (tid < 8) {
        float s = 0.f;
        #pragma unroll 16
        for (int c = 0; c < 64; ++c) s = fmaf(fS[c], W_k1[tid * 64 + c], s);
        hS[tid] = lrelu(s);
    } else if (tid >= 32 && tid < 40) {
        const int j = tid - 32;
        float s = 0.f;
        #pragma unroll 16
        for (int c = 0; c < 64; ++c) s = fmaf(faS[c], W_du1[j * 64 + c], s);
        hdS[j] = lrelu(s);
    }
    __syncthreads();

    for (int i = tid; i < 576; i += 512) {
        float s = 0.f;
        #pragma unroll
        for (int j = 0; j < 8; ++j) s = fmaf(hS[j], W_k2[i * 8 + j], s);
        g_kern[b * 576 + i] = s;
    }
    if (tid < 64) {
        float s = 0.f;
        #pragma unroll
        for (int j = 0; j < 8; ++j) s = fmaf(hdS[j], W_du2[tid * 8 + j], s);
        g_att[b * 64 + tid] = 1.0f / (1.0f + expf(-s));
    }
}

// ============================================================================
// Kernel B: depthwise-3x3 + lrelu (fp32) -> bf16 [c][px] (swizzled) ->
// warp-level mma.sync bf16 (D[256px][64o], K=64) -> fused epilogue.
// Block = (b, 2 rows), 512 threads, grid 1024. 43.8 KB dyn smem, 2 CTA/SM.
//
// smem map:
//   [0,     32768)  dwC bf16 [2 rows][64 c][128 px], 256B rows, xor (c&7)<<4
//   [32768, 40960)  W   bf16 [64 o][64 c], 128B rows, SW128 swizzle
//   [40960, 43264)  kS 576 f32
//   [43264, 43520)  attS 64
//   [43520, 43776)  biasS 64
// ============================================================================
#define C_OFF    0
#define W_OFF    32768
#define K_OFF    40960
#define ATT_OFF  43264
#define BIAS_OFF 43520
#define SMEM_TOTAL 43776

__global__ void __launch_bounds__(512, 2) main_kernel(
    const float* __restrict__ feat,    // [16,64,128,128]
    const float* __restrict__ b_conv,  // [64]
    float* __restrict__ out)
{
    extern __shared__ char smem[];
    const uint32_t smem_base = smem_u32(smem);

    float* kS    = (float*)(smem + K_OFF);
    float* attS  = (float*)(smem + ATT_OFF);
    float* biasS = (float*)(smem + BIAS_OFF);

    const int tid  = threadIdx.x;
    const int bid  = blockIdx.x;
    const int b    = bid >> 6;
    const int h0   = (bid & 63) * 2;
    const int lane = tid & 31;
    const int wid  = tid >> 5;   // 0..15

    // --- stage shared operands ---
    ((uint4*)(smem + W_OFF))[tid] = ((const uint4*)g_wswz)[tid];   // 8 KB
    for (int i = tid; i < 576; i += 512) kS[i] = g_kern[b * 576 + i];
    if (tid < 64) { attS[tid] = g_att[b * 64 + tid]; biasS[tid] = b_conv[tid]; }
    __syncthreads();

    // --- Stage 1: depthwise 3x3 + lrelu, bf16 into dwC [row][c][px] (swizzled) ---
    const float4* feat4 = (const float4*)feat;
    #pragma unroll
    for (int cp = 0; cp < 4; ++cp) {
        const int c = cp * 16 + wid;
        float4 v[4];
        float lf[4], rg[4];
        #pragma unroll
        for (int ri = 0; ri < 4; ++ri) {
            const int r = h0 - 1 + ri;
            if (r >= 0 && r < 128)
                v[ri] = feat4[(((size_t)b * 64 + c) * 128 + r) * 32 + lane];
            else
                v[ri] = make_float4(0.f, 0.f, 0.f, 0.f);
            lf[ri] = __shfl_up_sync(0xffffffffu, v[ri].w, 1);
            rg[ri] = __shfl_down_sync(0xffffffffu, v[ri].x, 1);
            if (lane == 0)  lf[ri] = 0.f;
            if (lane == 31) rg[ri] = 0.f;
        }
        const uint32_t wr_off = (uint32_t)(c * 256) +
            (((uint32_t)(lane * 8)) ^ ((uint32_t)(c & 7) << 4));
        #pragma unroll
        for (int row = 0; row < 2; ++row) {
            float4 a = make_float4(0.f, 0.f, 0.f, 0.f);
            #pragma unroll
            for (int kr = 0; kr < 3; ++kr) {
                const int ri = row + kr;
                const float q0 = kS[c * 9 + kr * 3 + 0];
                const float q1 = kS[c * 9 + kr * 3 + 1];
                const float q2 = kS[c * 9 + kr * 3 + 2];
                a.x = fmaf(q0, lf[ri],   fmaf(q1, v[ri].x, fmaf(q2, v[ri].y, a.x)));
                a.y = fmaf(q0, v[ri].x,  fmaf(q1, v[ri].y, fmaf(q2, v[ri].z, a.y)));
                a.z = fmaf(q0, v[ri].y,  fmaf(q1, v[ri].z, fmaf(q2, v[ri].w, a.z)));
                a.w = fmaf(q0, v[ri].z,  fmaf(q1, v[ri].w, fmaf(q2, rg[ri],  a.w)));
            }
            a.x = lrelu(a.x); a.y = lrelu(a.y); a.z = lrelu(a.z); a.w = lrelu(a.w);
            uint2 pk;
            pk.x = bf2(a.x, a.y);
            pk.y = bf2(a.z, a.w);
            *(uint2*)(smem + C_OFF + row * 16384 + wr_off) = pk;
        }
    }
    __syncthreads();

    // --- MMA: per warp one 16-px tile x 64 o, K=64 in 4 steps ---
    // A: dwC [c][px] via ldmatrix.x4.trans (stored [k][m]).
    // B: W [o][c] via ldmatrix.x4 (two n-tiles per instruction).
    const int px0 = (wid & 7) * 16;
    const int krl = (lane & 7) + ((lane & 16) >> 1);   // k-row (A) / o-row (B)
    const int m8  = (lane & 8);                        // +8 along m (A) / k (B)

    // A address: row = krl (+16 per ks), col = (px0 + m8)*2, xor (row&7)<<4.
    const uint32_t aBase = smem_base + C_OFF + (wid >> 3) * 16384 + krl * 256 +
        (((uint32_t)((px0 + m8) * 2)) ^ ((uint32_t)(krl & 7) << 4));
    // B address: row = krl (+16 per og), col = m8*2 + ks*32, xor (row&7)<<4.
    // ks*32 MUST be inside the xor (bits 5:6 overlap the swizzle mask).
    const uint32_t bRow  = smem_base + W_OFF + krl * 128;
    const uint32_t bXor  = ((uint32_t)(krl & 7)) << 4;
    const uint32_t bCol0 = (uint32_t)(m8 * 2);

    float acc[8][4];
    #pragma unroll
    for (int i = 0; i < 8; ++i)
        #pragma unroll
        for (int j = 0; j < 4; ++j) acc[i][j] = 0.f;

    #pragma unroll
    for (int ks = 0; ks < 4; ++ks) {
        uint32_t a0, a1, a2, a3;
        ldm_x4_t(a0, a1, a2, a3, aBase + ks * 4096);
        const uint32_t bColS = (bCol0 + (uint32_t)(ks * 32)) ^ bXor;
        #pragma unroll
        for (int og = 0; og < 4; ++og) {
            uint32_t b0, b1, b2, b3;
            ldm_x4(b0, b1, b2, b3, bRow + og * 2048 + bColS);
            mma_bf16(acc[og * 2],     a0, a1, a2, a3, b0, b1);
            mma_bf16(acc[og * 2 + 1], a0, a1, a2, a3, b2, b3);
        }
    }

    // --- epilogue: + bias + feat*att ---
    {
        const int g = lane >> 2;
        const int t = lane & 3;
        const int h = h0 + (wid >> 3);
        const int wb = px0 + g;
        const size_t rowbase = (((size_t)b * 64) * 128 + h) * 128;   // + o*16384 + w

        #pragma unroll
        for (int ot = 0; ot < 8; ++ot) {
            const int o = ot * 8 + 2 * t;
            #pragma unroll
            for (int r = 0; r < 2; ++r) {
                const int w = wb + r * 8;
                const size_t i0 = rowbase + (size_t)o * 16384 + w;
                const size_t i1 = i0 + 16384;
                out[i0] = acc[ot][2 * r]     + biasS[o]     + feat[i0] * attS[o];
                out[i1] = acc[ot][2 * r + 1] + biasS[o + 1] + feat[i1] * attS[o + 1];
            }
        }
    }
}

extern "C" void kernel_launch(void* const* d_in, const int* in_sizes, int n_in,
                              void* d_out, int out_size) {
    (void)in_sizes; (void)n_in; (void)out_size;
    const float* feat   = (const float*)d_in[0];
    const float* deg    = (const float*)d_in[1];
    const float* W_size = (const float*)d_in[2];
    const float* W_k1   = (const float*)d_in[3];
    const float* W_k2   = (const float*)d_in[4];
    const float* W_conv = (const float*)d_in[5];
    const float* b_conv = (const float*)d_in[6];
    const float* W_ac   = (const float*)d_in[7];
    const float* W_du1  = (const float*)d_in[8];
    const float* W_du2  = (const float*)d_in[9];
    float* out = (float*)d_out;

    mean_kernel<<<1024, 256>>>(deg);
    prep_kernel<<<16, 512>>>(W_size, W_k1, W_k2, W_ac, W_du1, W_du2, W_conv);
    main_kernel<<<16 * 64, 512, SMEM_TOTAL>>>(feat, b_conv, out);
}